// round 6
// baseline (speedup 1.0000x reference)
#include <cuda_runtime.h>
#include <cuda_bf16.h>
#include <mma.h>

using namespace nvcuda;

#define DD 64
#define MAXN 50000
#define MAXE 800000

// ---------------- scratch (device globals: no allocation allowed) ----------
__device__ __align__(16) float g_esrc[(size_t)MAXN * DD];
__device__ __align__(16) float g_edst[(size_t)MAXN * DD];
__device__ __align__(16) float g_Bh  [(size_t)MAXN * DD];
__device__ __align__(16) float g_xs  [(size_t)MAXN * DD];
__device__ __align__(16) float g_xpre[(size_t)MAXN * DD];
__device__ __align__(16) float g_num [(size_t)MAXN * DD];
__device__ __align__(16) float g_den [(size_t)MAXN * DD];
__device__ __align__(16) float g_m   [(size_t)MAXE * DD];
// [0:64) edge_sum [64:128) edge_sumsq [128:192) node_sum [192:256) node_sumsq
__device__ __align__(16) float g_stats[256];

__device__ __forceinline__ float sigmoidf_(float x) {
    return __fdividef(1.0f, 1.0f + __expf(-x));
}
__device__ __forceinline__ void red4(float* p, float a, float b, float c, float d) {
    asm volatile("{\n\t.reg .u64 q;\n\tcvta.to.global.u64 q, %0;\n\t"
                 "red.global.add.v4.f32 [q], {%1, %2, %3, %4};\n\t}"
                 :: "l"(p), "f"(a), "f"(b), "f"(c), "f"(d) : "memory");
}

// ---------------- node-side 4 GEMMs (unchanged R4) ---------------------------
__global__ __launch_bounds__(256) void node_gemm4(
    const float* __restrict__ nf,
    const float* __restrict__ Wsg, const float* __restrict__ bsg,
    const float* __restrict__ Wdg, const float* __restrict__ bdg,
    const float* __restrict__ Wsu, const float* __restrict__ bsu,
    const float* __restrict__ Wdu, const float* __restrict__ bdu,
    int n)
{
    __shared__ float shIn[64 * 65];
    __shared__ float shW[64 * 64];
    const int tid = threadIdx.x;
    const int tile0 = blockIdx.x * 64;

    for (int i = tid; i < 64 * 16; i += 256) {
        int r = i >> 4, c4 = (i & 15) << 2;
        float4 v = make_float4(0.f, 0.f, 0.f, 0.f);
        int row = tile0 + r;
        if (row < n) v = *reinterpret_cast<const float4*>(nf + (size_t)row * DD + c4);
        shIn[r * 65 + c4 + 0] = v.x; shIn[r * 65 + c4 + 1] = v.y;
        shIn[r * 65 + c4 + 2] = v.z; shIn[r * 65 + c4 + 3] = v.w;
    }

    const float* Ws[4] = {Wsg, Wdg, Wsu, Wdu};
    const float* bs[4] = {bsg, bdg, bsu, bdu};
    float* outs[4] = {g_esrc, g_edst, g_xs, g_Bh};

    const int cg = tid & 15, rg = tid >> 4;

    #pragma unroll
    for (int p = 0; p < 4; ++p) {
        __syncthreads();
        for (int i = tid; i < 64 * 16; i += 256)
            reinterpret_cast<float4*>(shW)[i] = reinterpret_cast<const float4*>(Ws[p])[i];
        __syncthreads();

        float4 bb = reinterpret_cast<const float4*>(bs[p])[cg];
        float acc[4][4];
        #pragma unroll
        for (int r = 0; r < 4; r++) {
            acc[r][0] = bb.x; acc[r][1] = bb.y; acc[r][2] = bb.z; acc[r][3] = bb.w;
        }
        #pragma unroll 8
        for (int k = 0; k < 64; k++) {
            float4 w = *reinterpret_cast<const float4*>(&shW[k * 64 + (cg << 2)]);
            #pragma unroll
            for (int r = 0; r < 4; r++) {
                float ev = shIn[(rg * 4 + r) * 65 + k];
                acc[r][0] += ev * w.x; acc[r][1] += ev * w.y;
                acc[r][2] += ev * w.z; acc[r][3] += ev * w.w;
            }
        }
        float* op = outs[p];
        #pragma unroll
        for (int r = 0; r < 4; r++) {
            int row = tile0 + rg * 4 + r;
            if (row < n) {
                *reinterpret_cast<float4*>(op + (size_t)row * DD + (cg << 2)) =
                    make_float4(acc[r][0], acc[r][1], acc[r][2], acc[r][3]);
            }
        }
    }

    float4 z = make_float4(0.f, 0.f, 0.f, 0.f);
    for (int i = tid; i < 64 * 16; i += 256) {
        int r = i >> 4, c4 = (i & 15) << 2;
        int row = tile0 + r;
        if (row < n) {
            *reinterpret_cast<float4*>(g_num + (size_t)row * DD + c4) = z;
            *reinterpret_cast<float4*>(g_den + (size_t)row * DD + c4) = z;
        }
    }
    if (blockIdx.x == 0 && tid < 256) g_stats[tid] = 0.f;
}

// ---------------- edge pass: wmma bf16 3-term split + R4 epilogue -----------
// 64 edges/block, 256 threads = 8 warps.
// warp w: rows [16*(w>>1), +16), cols [32*(w&1), +32) -> 2 accumulator frags.
// smem: A_hi/A_lo [64x72 bf16], B_hi/B_lo [64x72 bf16]; m-buffer [64x68 f32]
// overlays A region after MMA completes.
#define LDA 72
#define LDM 68

__global__ __launch_bounds__(256) void edge_pass1_mma(
    const float* __restrict__ ef, const int* __restrict__ eidx,
    const float* __restrict__ Weg, const float* __restrict__ beg,
    int nE)
{
    __shared__ __align__(16) __nv_bfloat16 shAhi[64 * LDA];
    __shared__ __align__(16) __nv_bfloat16 shAlo[64 * LDA];
    __shared__ __align__(16) __nv_bfloat16 shBhi[64 * LDA];
    __shared__ __align__(16) __nv_bfloat16 shBlo[64 * LDA];
    __shared__ int shS[64], shD[64];
    __shared__ float shSum[64], shSq[64];

    float* shM = reinterpret_cast<float*>(shAhi);   // 64*68 f32 = 17408B <= 18432B

    const int tid = threadIdx.x;
    const int wid = tid >> 5;
    const int tile0 = blockIdx.x * 64;

    if (tid < 64) {
        shSum[tid] = 0.f; shSq[tid] = 0.f;
        int e = tile0 + tid;
        shS[tid] = (e < nE) ? eidx[e] : 0;
        shD[tid] = (e < nE) ? eidx[(size_t)nE + e] : 0;
    }

    // A: edge_feats rows -> bf16 hi/lo
    for (int i = tid; i < 64 * 16; i += 256) {
        int r = i >> 4, c4 = (i & 15) << 2;
        float4 v = make_float4(0.f, 0.f, 0.f, 0.f);
        int e = tile0 + r;
        if (e < nE) v = *reinterpret_cast<const float4*>(ef + (size_t)e * DD + c4);
        __nv_bfloat16 h0 = __float2bfloat16(v.x), h1 = __float2bfloat16(v.y);
        __nv_bfloat16 h2 = __float2bfloat16(v.z), h3 = __float2bfloat16(v.w);
        int base = r * LDA + c4;
        shAhi[base + 0] = h0; shAhi[base + 1] = h1;
        shAhi[base + 2] = h2; shAhi[base + 3] = h3;
        shAlo[base + 0] = __float2bfloat16(v.x - __bfloat162float(h0));
        shAlo[base + 1] = __float2bfloat16(v.y - __bfloat162float(h1));
        shAlo[base + 2] = __float2bfloat16(v.z - __bfloat162float(h2));
        shAlo[base + 3] = __float2bfloat16(v.w - __bfloat162float(h3));
    }
    // B: W[k][n] row-major -> bf16 hi/lo (wmma matrix_b row_major)
    for (int i = tid; i < 64 * 16; i += 256) {
        int k = i >> 4, c4 = (i & 15) << 2;
        float4 w = *reinterpret_cast<const float4*>(Weg + k * DD + c4);
        __nv_bfloat16 h0 = __float2bfloat16(w.x), h1 = __float2bfloat16(w.y);
        __nv_bfloat16 h2 = __float2bfloat16(w.z), h3 = __float2bfloat16(w.w);
        int base = k * LDA + c4;
        shBhi[base + 0] = h0; shBhi[base + 1] = h1;
        shBhi[base + 2] = h2; shBhi[base + 3] = h3;
        shBlo[base + 0] = __float2bfloat16(w.x - __bfloat162float(h0));
        shBlo[base + 1] = __float2bfloat16(w.y - __bfloat162float(h1));
        shBlo[base + 2] = __float2bfloat16(w.z - __bfloat162float(h2));
        shBlo[base + 3] = __float2bfloat16(w.w - __bfloat162float(h3));
    }
    __syncthreads();

    // GEMM: 3-term split, fp32 accumulate
    const int mrow = (wid >> 1) * 16;
    const int ncol = (wid & 1) * 32;
    wmma::fragment<wmma::accumulator, 16, 16, 16, float> c0, c1;
    wmma::fill_fragment(c0, 0.0f);
    wmma::fill_fragment(c1, 0.0f);
    #pragma unroll
    for (int k = 0; k < 4; k++) {
        wmma::fragment<wmma::matrix_a, 16, 16, 16, __nv_bfloat16, wmma::row_major> ah, al;
        wmma::fragment<wmma::matrix_b, 16, 16, 16, __nv_bfloat16, wmma::row_major> bh0, bl0, bh1, bl1;
        wmma::load_matrix_sync(ah, &shAhi[mrow * LDA + k * 16], LDA);
        wmma::load_matrix_sync(al, &shAlo[mrow * LDA + k * 16], LDA);
        wmma::load_matrix_sync(bh0, &shBhi[(k * 16) * LDA + ncol], LDA);
        wmma::load_matrix_sync(bl0, &shBlo[(k * 16) * LDA + ncol], LDA);
        wmma::load_matrix_sync(bh1, &shBhi[(k * 16) * LDA + ncol + 16], LDA);
        wmma::load_matrix_sync(bl1, &shBlo[(k * 16) * LDA + ncol + 16], LDA);
        wmma::mma_sync(c0, ah, bh0, c0);
        wmma::mma_sync(c0, ah, bl0, c0);
        wmma::mma_sync(c0, al, bh0, c0);
        wmma::mma_sync(c1, ah, bh1, c1);
        wmma::mma_sync(c1, ah, bl1, c1);
        wmma::mma_sync(c1, al, bh1, c1);
    }
    __syncthreads();   // all warps done reading A/B before overlay store
    wmma::store_matrix_sync(&shM[mrow * LDM + ncol],      c0, LDM, wmma::mem_row_major);
    wmma::store_matrix_sync(&shM[mrow * LDM + ncol + 16], c1, LDM, wmma::mem_row_major);
    __syncthreads();

    // ---------- R4 epilogue: 16 threads/row, thread covers 4 rows -----------
    const int cg = tid & 15, rg = tid >> 4;
    float4 bb = reinterpret_cast<const float4*>(beg)[cg];
    float lsum[4] = {0.f, 0.f, 0.f, 0.f};
    float lsq[4]  = {0.f, 0.f, 0.f, 0.f};
    #pragma unroll
    for (int r = 0; r < 4; r++) {
        int li = rg * 4 + r;
        int e = tile0 + li;
        if (e >= nE) continue;
        int s = shS[li], d = shD[li];
        float4 mm = *reinterpret_cast<const float4*>(&shM[li * LDM + (cg << 2)]);
        float4 es = *reinterpret_cast<const float4*>(g_esrc + (size_t)s * DD + (cg << 2));
        float4 ed = *reinterpret_cast<const float4*>(g_edst + (size_t)d * DD + (cg << 2));
        float m0 = mm.x + bb.x + es.x + ed.x;
        float m1 = mm.y + bb.y + es.y + ed.y;
        float m2 = mm.z + bb.z + es.z + ed.z;
        float m3 = mm.w + bb.w + es.w + ed.w;
        *reinterpret_cast<float4*>(g_m + (size_t)e * DD + (cg << 2)) =
            make_float4(m0, m1, m2, m3);
        float s0 = sigmoidf_(m0), s1 = sigmoidf_(m1);
        float s2 = sigmoidf_(m2), s3 = sigmoidf_(m3);
        float4 bh = *reinterpret_cast<const float4*>(g_Bh + (size_t)s * DD + (cg << 2));
        red4(g_num + (size_t)d * DD + (cg << 2), bh.x * s0, bh.y * s1, bh.z * s2, bh.w * s3);
        red4(g_den + (size_t)d * DD + (cg << 2), s0, s1, s2, s3);
        lsum[0] += m0; lsum[1] += m1; lsum[2] += m2; lsum[3] += m3;
        lsq[0] += m0 * m0; lsq[1] += m1 * m1; lsq[2] += m2 * m2; lsq[3] += m3 * m3;
    }

    #pragma unroll
    for (int j = 0; j < 4; j++) {
        lsum[j] += __shfl_xor_sync(0xffffffffu, lsum[j], 16);
        lsq[j]  += __shfl_xor_sync(0xffffffffu, lsq[j], 16);
    }
    if ((tid & 16) == 0) {
        #pragma unroll
        for (int j = 0; j < 4; j++) {
            atomicAdd(&shSum[(cg << 2) + j], lsum[j]);
            atomicAdd(&shSq [(cg << 2) + j], lsq[j]);
        }
    }
    __syncthreads();
    if (tid < 16) {
        int t4 = tid << 2;
        red4(&g_stats[t4], shSum[t4], shSum[t4 + 1], shSum[t4 + 2], shSum[t4 + 3]);
    } else if (tid < 32) {
        int t4 = (tid - 16) << 2;
        red4(&g_stats[64 + t4], shSq[t4], shSq[t4 + 1], shSq[t4 + 2], shSq[t4 + 3]);
    }
}

// ---------------- node pre-activation (unchanged R4) -------------------------
__global__ __launch_bounds__(256) void node_pre(int nN)
{
    __shared__ float shSum[64], shSq[64];
    if (threadIdx.x < 64) { shSum[threadIdx.x] = 0.f; shSq[threadIdx.x] = 0.f; }
    __syncthreads();

    const int stride = gridDim.x * 256;
    const int tot = nN * 16;
    const int cg = threadIdx.x & 15;
    float l0 = 0.f, l1 = 0.f, l2 = 0.f, l3 = 0.f;
    float q0 = 0.f, q1 = 0.f, q2 = 0.f, q3 = 0.f;
    for (int idx = blockIdx.x * 256 + threadIdx.x; idx < tot; idx += stride) {
        float4 xs = reinterpret_cast<const float4*>(g_xs)[idx];
        float4 nu = reinterpret_cast<const float4*>(g_num)[idx];
        float4 de = reinterpret_cast<const float4*>(g_den)[idx];
        float4 v;
        v.x = xs.x + nu.x / (de.x + 1e-6f);
        v.y = xs.y + nu.y / (de.y + 1e-6f);
        v.z = xs.z + nu.z / (de.z + 1e-6f);
        v.w = xs.w + nu.w / (de.w + 1e-6f);
        reinterpret_cast<float4*>(g_xpre)[idx] = v;
        l0 += v.x; l1 += v.y; l2 += v.z; l3 += v.w;
        q0 += v.x * v.x; q1 += v.y * v.y; q2 += v.z * v.z; q3 += v.w * v.w;
    }
    l0 += __shfl_xor_sync(0xffffffffu, l0, 16); q0 += __shfl_xor_sync(0xffffffffu, q0, 16);
    l1 += __shfl_xor_sync(0xffffffffu, l1, 16); q1 += __shfl_xor_sync(0xffffffffu, q1, 16);
    l2 += __shfl_xor_sync(0xffffffffu, l2, 16); q2 += __shfl_xor_sync(0xffffffffu, q2, 16);
    l3 += __shfl_xor_sync(0xffffffffu, l3, 16); q3 += __shfl_xor_sync(0xffffffffu, q3, 16);
    if ((threadIdx.x & 16) == 0) {
        atomicAdd(&shSum[(cg << 2) + 0], l0); atomicAdd(&shSum[(cg << 2) + 1], l1);
        atomicAdd(&shSum[(cg << 2) + 2], l2); atomicAdd(&shSum[(cg << 2) + 3], l3);
        atomicAdd(&shSq [(cg << 2) + 0], q0); atomicAdd(&shSq [(cg << 2) + 1], q1);
        atomicAdd(&shSq [(cg << 2) + 2], q2); atomicAdd(&shSq [(cg << 2) + 3], q3);
    }
    __syncthreads();
    if (threadIdx.x < 16) {
        int t4 = threadIdx.x << 2;
        red4(&g_stats[128 + t4], shSum[t4], shSum[t4 + 1], shSum[t4 + 2], shSum[t4 + 3]);
    } else if (threadIdx.x < 32) {
        int t4 = (threadIdx.x - 16) << 2;
        red4(&g_stats[192 + t4], shSq[t4], shSq[t4 + 1], shSq[t4 + 2], shSq[t4 + 3]);
    }
}

// ---------------- merged outputs + fused BN finalize -------------------------
__global__ __launch_bounds__(256) void outputs_k(
    const float* __restrict__ nf, const float* __restrict__ ef,
    const float* __restrict__ gn, const float* __restrict__ btn,
    const float* __restrict__ ge, const float* __restrict__ bte,
    float* __restrict__ outx, float* __restrict__ outy,
    int nN, int nE)
{
    __shared__ float sEsc[64], sEsh[64], sNsc[64], sNsh[64];
    int t = threadIdx.x;
    if (t < 64) {
        float invE = 1.f / (float)nE;
        float me = g_stats[t] * invE;
        float ve = g_stats[64 + t] * invE - me * me;
        float sce = rsqrtf(ve + 1e-5f) * ge[t];
        sEsc[t] = sce; sEsh[t] = bte[t] - me * sce;
    } else if (t < 128) {
        int u = t - 64;
        float invN = 1.f / (float)nN;
        float mn = g_stats[128 + u] * invN;
        float vn = g_stats[192 + u] * invN - mn * mn;
        float scn = rsqrtf(vn + 1e-5f) * gn[u];
        sNsc[u] = scn; sNsh[u] = btn[u] - mn * scn;
    }
    __syncthreads();

    int idx = blockIdx.x * 256 + threadIdx.x;
    int nTot = nN * 16;
    if (idx < nTot) {
        int cg = idx & 15;
        float4 sc = *reinterpret_cast<const float4*>(&sNsc[cg << 2]);
        float4 sh = *reinterpret_cast<const float4*>(&sNsh[cg << 2]);
        float4 xp = reinterpret_cast<const float4*>(g_xpre)[idx];
        float4 nv = reinterpret_cast<const float4*>(nf)[idx];
        float t0 = xp.x * sc.x + sh.x;
        float t1 = xp.y * sc.y + sh.y;
        float t2 = xp.z * sc.z + sh.z;
        float t3 = xp.w * sc.w + sh.w;
        float4 o;
        o.x = nv.x + t0 * sigmoidf_(t0);
        o.y = nv.y + t1 * sigmoidf_(t1);
        o.z = nv.z + t2 * sigmoidf_(t2);
        o.w = nv.w + t3 * sigmoidf_(t3);
        reinterpret_cast<float4*>(outx)[idx] = o;
    } else {
        int j = idx - nTot;
        if (j >= nE * 16) return;
        int cg = j & 15;
        float4 sc = *reinterpret_cast<const float4*>(&sEsc[cg << 2]);
        float4 sh = *reinterpret_cast<const float4*>(&sEsh[cg << 2]);
        float4 mv = reinterpret_cast<const float4*>(g_m)[j];
        float4 ev = reinterpret_cast<const float4*>(ef)[j];
        float t0 = mv.x * sc.x + sh.x;
        float t1 = mv.y * sc.y + sh.y;
        float t2 = mv.z * sc.z + sh.z;
        float t3 = mv.w * sc.w + sh.w;
        float4 o;
        o.x = ev.x + t0 * sigmoidf_(t0);
        o.y = ev.y + t1 * sigmoidf_(t1);
        o.z = ev.z + t2 * sigmoidf_(t2);
        o.w = ev.w + t3 * sigmoidf_(t3);
        reinterpret_cast<float4*>(outy)[j] = o;
    }
}

// ---------------- launch -----------------------------------------------------
extern "C" void kernel_launch(void* const* d_in, const int* in_sizes, int n_in,
                              void* d_out, int out_size)
{
    (void)n_in; (void)out_size;
    const int* eidx  = (const int*)d_in[0];   // edge_index is int32 (JAX x64 disabled)
    const float* nf  = (const float*)d_in[1];
    const float* ef  = (const float*)d_in[2];
    const float* Wsg = (const float*)d_in[3];  const float* bsg = (const float*)d_in[4];
    const float* Wdg = (const float*)d_in[5];  const float* bdg = (const float*)d_in[6];
    const float* Weg = (const float*)d_in[7];  const float* beg = (const float*)d_in[8];
    const float* Wsu = (const float*)d_in[9];  const float* bsu = (const float*)d_in[10];
    const float* Wdu = (const float*)d_in[11]; const float* bdu = (const float*)d_in[12];
    const float* gmn = (const float*)d_in[13]; const float* btn = (const float*)d_in[14];
    const float* gme = (const float*)d_in[15]; const float* bte = (const float*)d_in[16];

    int nE = in_sizes[0] / 2;
    int nN = in_sizes[1] / DD;

    float* outx = (float*)d_out;
    float* outy = outx + (size_t)nN * DD;

    node_gemm4<<<(nN + 63) / 64, 256>>>(nf, Wsg, bsg, Wdg, bdg, Wsu, bsu, Wdu, bdu, nN);
    edge_pass1_mma<<<(nE + 63) / 64, 256>>>(ef, eidx, Weg, beg, nE);
    node_pre<<<391, 256>>>(nN);
    outputs_k<<<((nN + nE) * 16 + 255) / 256, 256>>>(nf, ef, gmn, btn, gme, bte,
                                                     outx, outy, nN, nE);
}

// round 7
// speedup vs baseline: 1.4919x; 1.4919x over previous
#include <cuda_runtime.h>
#include <cuda_fp16.h>
#include <mma.h>

using namespace nvcuda;

#define DD 64
#define MAXN 50000
#define MAXE 800000

// ---------------- scratch (device globals: no allocation allowed) ----------
__device__ __align__(16) float g_esrc[(size_t)MAXN * DD];
__device__ __align__(16) float g_edst[(size_t)MAXN * DD];
__device__ __align__(16) float g_Bh  [(size_t)MAXN * DD];
__device__ __align__(16) float g_xs  [(size_t)MAXN * DD];
__device__ __align__(16) float g_xpre[(size_t)MAXN * DD];
__device__ __align__(16) float g_num [(size_t)MAXN * DD];
__device__ __align__(16) float g_den [(size_t)MAXN * DD];
__device__ __align__(16) float g_m   [(size_t)MAXE * DD];
// [0:64) edge_sum [64:128) edge_sumsq [128:192) node_sum [192:256) node_sumsq
__device__ __align__(16) float g_stats[256];

__device__ __forceinline__ float sigmoidf_(float x) {
    return __fdividef(1.0f, 1.0f + __expf(-x));
}
__device__ __forceinline__ void red4(float* p, float a, float b, float c, float d) {
    asm volatile("{\n\t.reg .u64 q;\n\tcvta.to.global.u64 q, %0;\n\t"
                 "red.global.add.v4.f32 [q], {%1, %2, %3, %4};\n\t}"
                 :: "l"(p), "f"(a), "f"(b), "f"(c), "f"(d) : "memory");
}

// ---------------- node-side 4 GEMMs (unchanged R4) ---------------------------
__global__ __launch_bounds__(256) void node_gemm4(
    const float* __restrict__ nf,
    const float* __restrict__ Wsg, const float* __restrict__ bsg,
    const float* __restrict__ Wdg, const float* __restrict__ bdg,
    const float* __restrict__ Wsu, const float* __restrict__ bsu,
    const float* __restrict__ Wdu, const float* __restrict__ bdu,
    int n)
{
    __shared__ float shIn[64 * 65];
    __shared__ float shW[64 * 64];
    const int tid = threadIdx.x;
    const int tile0 = blockIdx.x * 64;

    for (int i = tid; i < 64 * 16; i += 256) {
        int r = i >> 4, c4 = (i & 15) << 2;
        float4 v = make_float4(0.f, 0.f, 0.f, 0.f);
        int row = tile0 + r;
        if (row < n) v = *reinterpret_cast<const float4*>(nf + (size_t)row * DD + c4);
        shIn[r * 65 + c4 + 0] = v.x; shIn[r * 65 + c4 + 1] = v.y;
        shIn[r * 65 + c4 + 2] = v.z; shIn[r * 65 + c4 + 3] = v.w;
    }

    const float* Ws[4] = {Wsg, Wdg, Wsu, Wdu};
    const float* bs[4] = {bsg, bdg, bsu, bdu};
    float* outs[4] = {g_esrc, g_edst, g_xs, g_Bh};

    const int cg = tid & 15, rg = tid >> 4;

    #pragma unroll
    for (int p = 0; p < 4; ++p) {
        __syncthreads();
        for (int i = tid; i < 64 * 16; i += 256)
            reinterpret_cast<float4*>(shW)[i] = reinterpret_cast<const float4*>(Ws[p])[i];
        __syncthreads();

        float4 bb = reinterpret_cast<const float4*>(bs[p])[cg];
        float acc[4][4];
        #pragma unroll
        for (int r = 0; r < 4; r++) {
            acc[r][0] = bb.x; acc[r][1] = bb.y; acc[r][2] = bb.z; acc[r][3] = bb.w;
        }
        #pragma unroll 8
        for (int k = 0; k < 64; k++) {
            float4 w = *reinterpret_cast<const float4*>(&shW[k * 64 + (cg << 2)]);
            #pragma unroll
            for (int r = 0; r < 4; r++) {
                float ev = shIn[(rg * 4 + r) * 65 + k];
                acc[r][0] += ev * w.x; acc[r][1] += ev * w.y;
                acc[r][2] += ev * w.z; acc[r][3] += ev * w.w;
            }
        }
        float* op = outs[p];
        #pragma unroll
        for (int r = 0; r < 4; r++) {
            int row = tile0 + rg * 4 + r;
            if (row < n) {
                *reinterpret_cast<float4*>(op + (size_t)row * DD + (cg << 2)) =
                    make_float4(acc[r][0], acc[r][1], acc[r][2], acc[r][3]);
            }
        }
    }

    float4 z = make_float4(0.f, 0.f, 0.f, 0.f);
    for (int i = tid; i < 64 * 16; i += 256) {
        int r = i >> 4, c4 = (i & 15) << 2;
        int row = tile0 + r;
        if (row < n) {
            *reinterpret_cast<float4*>(g_num + (size_t)row * DD + c4) = z;
            *reinterpret_cast<float4*>(g_den + (size_t)row * DD + c4) = z;
        }
    }
    if (blockIdx.x == 0 && tid < 256) g_stats[tid] = 0.f;
}

// ---------------- edge pass: wmma fp16 2-term split + R4 epilogue -----------
// 64 edges/block, 256 threads = 8 warps.
// m = Ah*Bh + Ah*Bl  (A residual dropped: |err| ~ 2^-12 * sqrt(K) * |b| ~ 2e-4)
// warp w: rows [16*(w>>1), +16), cols [32*(w&1), +32).
// smem carved from one buffer; m-buffer (64x68 f32) overlays Ahi+Bhi after MMA.
#define LDA 72
#define LDM 68

__global__ __launch_bounds__(256) void edge_pass1_mma(
    const float* __restrict__ ef, const int* __restrict__ eidx,
    const float* __restrict__ Weg, const float* __restrict__ beg,
    int nE)
{
    __shared__ __align__(16) char buf[64 * LDA * 2 * 3];   // Ahi | Bhi | Blo (27648B)
    __shared__ int shS[64], shD[64];
    __shared__ float shSum[64], shSq[64];

    __half* shAhi = reinterpret_cast<__half*>(buf);
    __half* shBhi = reinterpret_cast<__half*>(buf + 64 * LDA * 2);
    __half* shBlo = reinterpret_cast<__half*>(buf + 64 * LDA * 4);
    float*  shM   = reinterpret_cast<float*>(buf);          // 64*68*4=17408B <= 18432B (Ahi+Bhi)

    const int tid = threadIdx.x;
    const int wid = tid >> 5;
    const int tile0 = blockIdx.x * 64;

    if (tid < 64) {
        shSum[tid] = 0.f; shSq[tid] = 0.f;
        int e = tile0 + tid;
        shS[tid] = (e < nE) ? eidx[e] : 0;
        shD[tid] = (e < nE) ? eidx[(size_t)nE + e] : 0;
    }

    // A: edge_feats rows -> fp16 hi only
    for (int i = tid; i < 64 * 16; i += 256) {
        int r = i >> 4, c4 = (i & 15) << 2;
        float4 v = make_float4(0.f, 0.f, 0.f, 0.f);
        int e = tile0 + r;
        if (e < nE) v = *reinterpret_cast<const float4*>(ef + (size_t)e * DD + c4);
        int base = r * LDA + c4;
        *reinterpret_cast<__half2*>(&shAhi[base])     = __floats2half2_rn(v.x, v.y);
        *reinterpret_cast<__half2*>(&shAhi[base + 2]) = __floats2half2_rn(v.z, v.w);
    }
    // B: W[k][n] row-major -> fp16 hi/lo
    for (int i = tid; i < 64 * 16; i += 256) {
        int k = i >> 4, c4 = (i & 15) << 2;
        float4 w = *reinterpret_cast<const float4*>(Weg + k * DD + c4);
        __half h0 = __float2half_rn(w.x), h1 = __float2half_rn(w.y);
        __half h2 = __float2half_rn(w.z), h3 = __float2half_rn(w.w);
        int base = k * LDA + c4;
        __half2 hh;
        hh.x = h0; hh.y = h1; *reinterpret_cast<__half2*>(&shBhi[base])     = hh;
        hh.x = h2; hh.y = h3; *reinterpret_cast<__half2*>(&shBhi[base + 2]) = hh;
        hh.x = __float2half_rn(w.x - __half2float(h0));
        hh.y = __float2half_rn(w.y - __half2float(h1));
        *reinterpret_cast<__half2*>(&shBlo[base]) = hh;
        hh.x = __float2half_rn(w.z - __half2float(h2));
        hh.y = __float2half_rn(w.w - __half2float(h3));
        *reinterpret_cast<__half2*>(&shBlo[base + 2]) = hh;
    }
    __syncthreads();

    // GEMM: 2-term split, fp32 accumulate
    const int mrow = (wid >> 1) * 16;
    const int ncol = (wid & 1) * 32;
    wmma::fragment<wmma::accumulator, 16, 16, 16, float> c0, c1;
    wmma::fill_fragment(c0, 0.0f);
    wmma::fill_fragment(c1, 0.0f);
    #pragma unroll
    for (int k = 0; k < 4; k++) {
        wmma::fragment<wmma::matrix_a, 16, 16, 16, __half, wmma::row_major> ah;
        wmma::fragment<wmma::matrix_b, 16, 16, 16, __half, wmma::row_major> bh0, bl0, bh1, bl1;
        wmma::load_matrix_sync(ah, &shAhi[mrow * LDA + k * 16], LDA);
        wmma::load_matrix_sync(bh0, &shBhi[(k * 16) * LDA + ncol], LDA);
        wmma::load_matrix_sync(bl0, &shBlo[(k * 16) * LDA + ncol], LDA);
        wmma::load_matrix_sync(bh1, &shBhi[(k * 16) * LDA + ncol + 16], LDA);
        wmma::load_matrix_sync(bl1, &shBlo[(k * 16) * LDA + ncol + 16], LDA);
        wmma::mma_sync(c0, ah, bh0, c0);
        wmma::mma_sync(c0, ah, bl0, c0);
        wmma::mma_sync(c1, ah, bh1, c1);
        wmma::mma_sync(c1, ah, bl1, c1);
    }
    __syncthreads();   // all warps done reading A/B before overlay store
    wmma::store_matrix_sync(&shM[mrow * LDM + ncol],      c0, LDM, wmma::mem_row_major);
    wmma::store_matrix_sync(&shM[mrow * LDM + ncol + 16], c1, LDM, wmma::mem_row_major);
    __syncthreads();

    // ---------- R4 epilogue: 16 threads/row, thread covers 4 rows -----------
    const int cg = tid & 15, rg = tid >> 4;
    float4 bb = reinterpret_cast<const float4*>(beg)[cg];
    float lsum[4] = {0.f, 0.f, 0.f, 0.f};
    float lsq[4]  = {0.f, 0.f, 0.f, 0.f};
    #pragma unroll
    for (int r = 0; r < 4; r++) {
        int li = rg * 4 + r;
        int e = tile0 + li;
        if (e >= nE) continue;
        int s = shS[li], d = shD[li];
        float4 mm = *reinterpret_cast<const float4*>(&shM[li * LDM + (cg << 2)]);
        float4 es = *reinterpret_cast<const float4*>(g_esrc + (size_t)s * DD + (cg << 2));
        float4 ed = *reinterpret_cast<const float4*>(g_edst + (size_t)d * DD + (cg << 2));
        float m0 = mm.x + bb.x + es.x + ed.x;
        float m1 = mm.y + bb.y + es.y + ed.y;
        float m2 = mm.z + bb.z + es.z + ed.z;
        float m3 = mm.w + bb.w + es.w + ed.w;
        *reinterpret_cast<float4*>(g_m + (size_t)e * DD + (cg << 2)) =
            make_float4(m0, m1, m2, m3);
        float s0 = sigmoidf_(m0), s1 = sigmoidf_(m1);
        float s2 = sigmoidf_(m2), s3 = sigmoidf_(m3);
        float4 bh = *reinterpret_cast<const float4*>(g_Bh + (size_t)s * DD + (cg << 2));
        red4(g_num + (size_t)d * DD + (cg << 2), bh.x * s0, bh.y * s1, bh.z * s2, bh.w * s3);
        red4(g_den + (size_t)d * DD + (cg << 2), s0, s1, s2, s3);
        lsum[0] += m0; lsum[1] += m1; lsum[2] += m2; lsum[3] += m3;
        lsq[0] += m0 * m0; lsq[1] += m1 * m1; lsq[2] += m2 * m2; lsq[3] += m3 * m3;
    }

    #pragma unroll
    for (int j = 0; j < 4; j++) {
        lsum[j] += __shfl_xor_sync(0xffffffffu, lsum[j], 16);
        lsq[j]  += __shfl_xor_sync(0xffffffffu, lsq[j], 16);
    }
    if ((tid & 16) == 0) {
        #pragma unroll
        for (int j = 0; j < 4; j++) {
            atomicAdd(&shSum[(cg << 2) + j], lsum[j]);
            atomicAdd(&shSq [(cg << 2) + j], lsq[j]);
        }
    }
    __syncthreads();
    if (tid < 16) {
        int t4 = tid << 2;
        red4(&g_stats[t4], shSum[t4], shSum[t4 + 1], shSum[t4 + 2], shSum[t4 + 3]);
    } else if (tid < 32) {
        int t4 = (tid - 16) << 2;
        red4(&g_stats[64 + t4], shSq[t4], shSq[t4 + 1], shSq[t4 + 2], shSq[t4 + 3]);
    }
}

// ---------------- node pre-activation (unchanged R4) -------------------------
__global__ __launch_bounds__(256) void node_pre(int nN)
{
    __shared__ float shSum[64], shSq[64];
    if (threadIdx.x < 64) { shSum[threadIdx.x] = 0.f; shSq[threadIdx.x] = 0.f; }
    __syncthreads();

    const int stride = gridDim.x * 256;
    const int tot = nN * 16;
    const int cg = threadIdx.x & 15;
    float l0 = 0.f, l1 = 0.f, l2 = 0.f, l3 = 0.f;
    float q0 = 0.f, q1 = 0.f, q2 = 0.f, q3 = 0.f;
    for (int idx = blockIdx.x * 256 + threadIdx.x; idx < tot; idx += stride) {
        float4 xs = reinterpret_cast<const float4*>(g_xs)[idx];
        float4 nu = reinterpret_cast<const float4*>(g_num)[idx];
        float4 de = reinterpret_cast<const float4*>(g_den)[idx];
        float4 v;
        v.x = xs.x + nu.x / (de.x + 1e-6f);
        v.y = xs.y + nu.y / (de.y + 1e-6f);
        v.z = xs.z + nu.z / (de.z + 1e-6f);
        v.w = xs.w + nu.w / (de.w + 1e-6f);
        reinterpret_cast<float4*>(g_xpre)[idx] = v;
        l0 += v.x; l1 += v.y; l2 += v.z; l3 += v.w;
        q0 += v.x * v.x; q1 += v.y * v.y; q2 += v.z * v.z; q3 += v.w * v.w;
    }
    l0 += __shfl_xor_sync(0xffffffffu, l0, 16); q0 += __shfl_xor_sync(0xffffffffu, q0, 16);
    l1 += __shfl_xor_sync(0xffffffffu, l1, 16); q1 += __shfl_xor_sync(0xffffffffu, q1, 16);
    l2 += __shfl_xor_sync(0xffffffffu, l2, 16); q2 += __shfl_xor_sync(0xffffffffu, q2, 16);
    l3 += __shfl_xor_sync(0xffffffffu, l3, 16); q3 += __shfl_xor_sync(0xffffffffu, q3, 16);
    if ((threadIdx.x & 16) == 0) {
        atomicAdd(&shSum[(cg << 2) + 0], l0); atomicAdd(&shSum[(cg << 2) + 1], l1);
        atomicAdd(&shSum[(cg << 2) + 2], l2); atomicAdd(&shSum[(cg << 2) + 3], l3);
        atomicAdd(&shSq [(cg << 2) + 0], q0); atomicAdd(&shSq [(cg << 2) + 1], q1);
        atomicAdd(&shSq [(cg << 2) + 2], q2); atomicAdd(&shSq [(cg << 2) + 3], q3);
    }
    __syncthreads();
    if (threadIdx.x < 16) {
        int t4 = threadIdx.x << 2;
        red4(&g_stats[128 + t4], shSum[t4], shSum[t4 + 1], shSum[t4 + 2], shSum[t4 + 3]);
    } else if (threadIdx.x < 32) {
        int t4 = (threadIdx.x - 16) << 2;
        red4(&g_stats[192 + t4], shSq[t4], shSq[t4 + 1], shSq[t4 + 2], shSq[t4 + 3]);
    }
}

// ---------------- merged outputs + fused BN finalize -------------------------
__global__ __launch_bounds__(256) void outputs_k(
    const float* __restrict__ nf, const float* __restrict__ ef,
    const float* __restrict__ gn, const float* __restrict__ btn,
    const float* __restrict__ ge, const float* __restrict__ bte,
    float* __restrict__ outx, float* __restrict__ outy,
    int nN, int nE)
{
    __shared__ float sEsc[64], sEsh[64], sNsc[64], sNsh[64];
    int t = threadIdx.x;
    if (t < 64) {
        float invE = 1.f / (float)nE;
        float me = g_stats[t] * invE;
        float ve = g_stats[64 + t] * invE - me * me;
        float sce = rsqrtf(ve + 1e-5f) * ge[t];
        sEsc[t] = sce; sEsh[t] = bte[t] - me * sce;
    } else if (t < 128) {
        int u = t - 64;
        float invN = 1.f / (float)nN;
        float mn = g_stats[128 + u] * invN;
        float vn = g_stats[192 + u] * invN - mn * mn;
        float scn = rsqrtf(vn + 1e-5f) * gn[u];
        sNsc[u] = scn; sNsh[u] = btn[u] - mn * scn;
    }
    __syncthreads();

    int idx = blockIdx.x * 256 + threadIdx.x;
    int nTot = nN * 16;
    if (idx < nTot) {
        int cg = idx & 15;
        float4 sc = *reinterpret_cast<const float4*>(&sNsc[cg << 2]);
        float4 sh = *reinterpret_cast<const float4*>(&sNsh[cg << 2]);
        float4 xp = reinterpret_cast<const float4*>(g_xpre)[idx];
        float4 nv = reinterpret_cast<const float4*>(nf)[idx];
        float t0 = xp.x * sc.x + sh.x;
        float t1 = xp.y * sc.y + sh.y;
        float t2 = xp.z * sc.z + sh.z;
        float t3 = xp.w * sc.w + sh.w;
        float4 o;
        o.x = nv.x + t0 * sigmoidf_(t0);
        o.y = nv.y + t1 * sigmoidf_(t1);
        o.z = nv.z + t2 * sigmoidf_(t2);
        o.w = nv.w + t3 * sigmoidf_(t3);
        reinterpret_cast<float4*>(outx)[idx] = o;
    } else {
        int j = idx - nTot;
        if (j >= nE * 16) return;
        int cg = j & 15;
        float4 sc = *reinterpret_cast<const float4*>(&sEsc[cg << 2]);
        float4 sh = *reinterpret_cast<const float4*>(&sEsh[cg << 2]);
        float4 mv = reinterpret_cast<const float4*>(g_m)[j];
        float4 ev = reinterpret_cast<const float4*>(ef)[j];
        float t0 = mv.x * sc.x + sh.x;
        float t1 = mv.y * sc.y + sh.y;
        float t2 = mv.z * sc.z + sh.z;
        float t3 = mv.w * sc.w + sh.w;
        float4 o;
        o.x = ev.x + t0 * sigmoidf_(t0);
        o.y = ev.y + t1 * sigmoidf_(t1);
        o.z = ev.z + t2 * sigmoidf_(t2);
        o.w = ev.w + t3 * sigmoidf_(t3);
        reinterpret_cast<float4*>(outy)[j] = o;
    }
}

// ---------------- launch -----------------------------------------------------
extern "C" void kernel_launch(void* const* d_in, const int* in_sizes, int n_in,
                              void* d_out, int out_size)
{
    (void)n_in; (void)out_size;
    const int* eidx  = (const int*)d_in[0];   // edge_index is int32 (JAX x64 disabled)
    const float* nf  = (const float*)d_in[1];
    const float* ef  = (const float*)d_in[2];
    const float* Wsg = (const float*)d_in[3];  const float* bsg = (const float*)d_in[4];
    const float* Wdg = (const float*)d_in[5];  const float* bdg = (const float*)d_in[6];
    const float* Weg = (const float*)d_in[7];  const float* beg = (const float*)d_in[8];
    const float* Wsu = (const float*)d_in[9];  const float* bsu = (const float*)d_in[10];
    const float* Wdu = (const float*)d_in[11]; const float* bdu = (const float*)d_in[12];
    const float* gmn = (const float*)d_in[13]; const float* btn = (const float*)d_in[14];
    const float* gme = (const float*)d_in[15]; const float* bte = (const float*)d_in[16];

    int nE = in_sizes[0] / 2;
    int nN = in_sizes[1] / DD;

    float* outx = (float*)d_out;
    float* outy = outx + (size_t)nN * DD;

    node_gemm4<<<(nN + 63) / 64, 256>>>(nf, Wsg, bsg, Wdg, bdg, Wsu, bsu, Wdu, bdu, nN);
    edge_pass1_mma<<<(nE + 63) / 64, 256>>>(ef, eidx, Weg, beg, nE);
    node_pre<<<391, 256>>>(nN);
    outputs_k<<<((nN + nE) * 16 + 255) / 256, 256>>>(nf, ef, gmn, btn, gme, bte,
                                                     outx, outy, nN, nE);
}